// round 1
// baseline (speedup 1.0000x reference)
#include <cuda_runtime.h>
#include <math.h>
#include <stdint.h>

// ---------------- problem constants ----------------
#define BATCH 16384
#define HDIM  4096
#define DDIM  1024
#define KCB   512
#define DIN   1090
#define DINP  1152   // padded input dim (multiple of 128)

// output layout (tuple flattened): q_st, loss, perplexity, new_embeddings, cs_stable
#define OUT_Q    0
#define OUT_LOSS 16777216
#define OUT_PERP 16777217
#define OUT_EMB  16777218
#define OUT_CS   17301506

// ---------------- scratch (device globals; no allocation) ----------------
__device__ float g_X0 [BATCH * DINP];
__device__ float g_W0p[DINP * HDIM];
__device__ float g_A1 [BATCH * HDIM];
__device__ float g_A2 [BATCH * HDIM];
__device__ float g_Z  [BATCH * DDIM];
__device__ float g_S  [BATCH * KCB];
__device__ float g_ET [KCB * DDIM];
__device__ float g_e2 [KCB];
__device__ int   g_idx[BATCH];
__device__ float g_counts[KCB];
__device__ float g_cs [KCB];
__device__ float g_rowloss[BATCH];
__device__ float g_dwT[KCB * DDIM];

// ---------------- small prep kernels ----------------
__global__ void zero_counts_kernel() {
    g_counts[blockIdx.x * 256 + threadIdx.x] = 0.0f;
}

// build padded hstack [B, 1152]
__global__ void pack_x0_kernel(const float* __restrict__ obs,
                               const float* __restrict__ act,
                               const float* __restrict__ nobs,
                               const float* __restrict__ rew,
                               const float* __restrict__ term) {
    int c = blockIdx.x * 128 + threadIdx.x;   // 0..1151 (grid.x = 9)
    int r = blockIdx.y;                        // 0..16383
    float v;
    if (c < 512)        v = obs [r * 512 + c];
    else if (c < 576)   v = act [r * 64  + (c - 512)];
    else if (c < 1088)  v = nobs[r * 512 + (c - 576)];
    else if (c == 1088) v = rew [r];
    else if (c == 1089) v = term[r];
    else                v = 0.0f;
    g_X0[(size_t)r * DINP + c] = v;
}

// pad w0 [1090,4096] -> [1152,4096]
__global__ void pack_w0_kernel(const float* __restrict__ w0) {
    int c = blockIdx.x * 128 + threadIdx.x;   // grid.x = 32
    int r = blockIdx.y;                        // 0..1151
    g_W0p[(size_t)r * HDIM + c] = (r < DIN) ? w0[(size_t)r * HDIM + c] : 0.0f;
}

// ET[k][d] = E[d][k]  (tiled transpose)
__global__ void prep_et_kernel(const float* __restrict__ E) {
    __shared__ float t[32][33];
    int k0 = blockIdx.x * 32, d0 = blockIdx.y * 32;
    int tx = threadIdx.x, ty = threadIdx.y;   // block (32,8)
#pragma unroll
    for (int i = 0; i < 4; i++)
        t[ty + i * 8][tx] = E[(size_t)(d0 + ty + i * 8) * KCB + k0 + tx];
    __syncthreads();
#pragma unroll
    for (int i = 0; i < 4; i++)
        g_ET[(size_t)(k0 + ty + i * 8) * DDIM + d0 + tx] = t[tx][ty + i * 8];
}

// e2[k] = sum_d E[d][k]^2
__global__ void prep_e2_kernel(const float* __restrict__ E) {
    int k = blockIdx.x * 256 + threadIdx.x;   // grid.x = 2
    float s = 0.0f;
    for (int d = 0; d < DDIM; d++) {
        float v = E[(size_t)d * KCB + k];
        s = fmaf(v, v, s);
    }
    g_e2[k] = s;
}

// ---------------- SGEMM: C[M,N] = A[M,K] @ B[K,N] (+bias)(+relu) ----------------
// 128x128 CTA tile, BK=8, 256 threads, 8x8 per thread.
template<bool RELU>
__global__ __launch_bounds__(256, 2)
void sgemm_kernel(const float* __restrict__ A, const float* __restrict__ B,
                  const float* __restrict__ bias, float* __restrict__ C,
                  int N, int K) {
    __shared__ float As[8][128];
    __shared__ float Bs[8][128];
    const int tid = threadIdx.x;
    const int bx = blockIdx.x, by = blockIdx.y;
    const float* Ab = A + (size_t)by * 128 * K;
    const float* Bb = B + (size_t)bx * 128;
    const int aRow = tid >> 1, aCol = (tid & 1) * 4;
    const int bRow = tid >> 5, bCol = (tid & 31) * 4;
    const int tx = (tid & 15) * 8, ty = (tid >> 4) * 8;
    float acc[8][8] = {};

    for (int kt = 0; kt < K; kt += 8) {
        float4 av = *reinterpret_cast<const float4*>(Ab + (size_t)aRow * K + kt + aCol);
        float4 bv = *reinterpret_cast<const float4*>(Bb + (size_t)(kt + bRow) * N + bCol);
        As[aCol + 0][aRow] = av.x;
        As[aCol + 1][aRow] = av.y;
        As[aCol + 2][aRow] = av.z;
        As[aCol + 3][aRow] = av.w;
        *reinterpret_cast<float4*>(&Bs[bRow][bCol]) = bv;
        __syncthreads();
#pragma unroll
        for (int kk = 0; kk < 8; kk++) {
            float a[8], b[8];
            *reinterpret_cast<float4*>(&a[0]) = *reinterpret_cast<const float4*>(&As[kk][ty]);
            *reinterpret_cast<float4*>(&a[4]) = *reinterpret_cast<const float4*>(&As[kk][ty + 4]);
            *reinterpret_cast<float4*>(&b[0]) = *reinterpret_cast<const float4*>(&Bs[kk][tx]);
            *reinterpret_cast<float4*>(&b[4]) = *reinterpret_cast<const float4*>(&Bs[kk][tx + 4]);
#pragma unroll
            for (int i = 0; i < 8; i++)
#pragma unroll
                for (int j = 0; j < 8; j++)
                    acc[i][j] = fmaf(a[i], b[j], acc[i][j]);
        }
        __syncthreads();
    }

    float bb[8];
#pragma unroll
    for (int j = 0; j < 8; j++) bb[j] = bias ? bias[bx * 128 + tx + j] : 0.0f;
#pragma unroll
    for (int i = 0; i < 8; i++) {
        float o[8];
#pragma unroll
        for (int j = 0; j < 8; j++) {
            float v = acc[i][j] + bb[j];
            if (RELU) v = fmaxf(v, 0.0f);
            o[j] = v;
        }
        float* Cp = C + (size_t)(by * 128 + ty + i) * N + bx * 128 + tx;
        *reinterpret_cast<float4*>(Cp)     = *reinterpret_cast<float4*>(&o[0]);
        *reinterpret_cast<float4*>(Cp + 4) = *reinterpret_cast<float4*>(&o[4]);
    }
}

// ---------------- VQ: per-row argmin + gather + loss partial + histogram ----------------
__global__ void vq_row_kernel(float* __restrict__ qout) {
    const int row = blockIdx.x;
    const int tid = threadIdx.x;              // 128 threads
    const float* Sr = g_S + (size_t)row * KCB;

    float best = 3.4e38f;
    int   bi   = 0;
    for (int k = tid; k < KCB; k += 128) {
        float dv = fmaf(-2.0f, Sr[k], g_e2[k]);   // ||z||^2 term is row-constant
        if (dv < best) { best = dv; bi = k; }
    }
    __shared__ float sv[128];
    __shared__ int   si[128];
    sv[tid] = best; si[tid] = bi;
    __syncthreads();
    for (int s = 64; s > 0; s >>= 1) {
        if (tid < s) {
            float ov = sv[tid + s]; int oi = si[tid + s];
            if (ov < sv[tid] || (ov == sv[tid] && oi < si[tid])) { sv[tid] = ov; si[tid] = oi; }
        }
        __syncthreads();
    }
    const int idx = si[0];
    if (tid == 0) {
        g_idx[row] = idx;
        atomicAdd(&g_counts[idx], 1.0f);   // integer counts: exact regardless of order
    }

    const float* e = g_ET + (size_t)idx * DDIM;
    const float* z = g_Z  + (size_t)row * DDIM;
    float ls = 0.0f;
    for (int d = tid; d < DDIM; d += 128) {
        float q = e[d], zz = z[d];
        qout[(size_t)row * DDIM + d] = q;
        float t = q - zz;
        ls = fmaf(t, t, ls);
    }
    __syncthreads();
    sv[tid] = ls;
    __syncthreads();
    for (int s = 64; s > 0; s >>= 1) {
        if (tid < s) sv[tid] += sv[tid + s];
        __syncthreads();
    }
    if (tid == 0) g_rowloss[row] = sv[0];
}

// ---------------- stats: n, perplexity, loss, cs_stable ----------------
__global__ void vq_stats_kernel(const float* __restrict__ ema_cs, float* __restrict__ out) {
    const int k = threadIdx.x;                // 512 threads, 1 block
    __shared__ float red[512];
    __shared__ float shn, shent;

    float cnt = g_counts[k];
    float cs  = 0.99f * ema_cs[k] + 0.01f * cnt;

    red[k] = cs; __syncthreads();
    for (int s = 256; s > 0; s >>= 1) { if (k < s) red[k] += red[k + s]; __syncthreads(); }
    if (k == 0) shn = red[0];
    __syncthreads();

    float p = cnt * (1.0f / 16384.0f);
    red[k] = p * logf(p + 1e-10f);
    __syncthreads();
    for (int s = 256; s > 0; s >>= 1) { if (k < s) red[k] += red[k + s]; __syncthreads(); }
    if (k == 0) shent = red[0];
    __syncthreads();

    float ls = 0.0f;
    for (int r = k; r < BATCH; r += 512) ls += g_rowloss[r];
    red[k] = ls; __syncthreads();
    for (int s = 256; s > 0; s >>= 1) { if (k < s) red[k] += red[k + s]; __syncthreads(); }

    float n   = shn;
    float csn = (cs + 1e-5f) / (n + 512.0f * 1e-5f) * n;
    g_cs[k] = csn;
    out[OUT_CS + k] = csn;
    if (k == 0) {
        out[OUT_LOSS] = 0.25f * red[0] / 16777216.0f;   // / (B*D)
        out[OUT_PERP] = expf(-shent);
    }
}

// ---------------- dw = z.T @ enc, deterministic ballot scan ----------------
// one block per codebook entry k; rows processed in ascending order -> fixed fp32 sum order
__global__ void vq_dw_kernel() {
    const int k = blockIdx.x;
    const int tid = threadIdx.x;              // 256 threads
    float a0 = 0.f, a1 = 0.f, a2 = 0.f, a3 = 0.f;
    __shared__ unsigned smask[8];

    for (int b0 = 0; b0 < BATCH; b0 += 256) {
        int mi = g_idx[b0 + tid];
        unsigned m = __ballot_sync(0xffffffffu, mi == k);
        if ((tid & 31) == 0) smask[tid >> 5] = m;
        __syncthreads();
#pragma unroll
        for (int w = 0; w < 8; w++) {
            unsigned mm = smask[w];
            while (mm) {
                int bit = __ffs(mm) - 1;
                mm &= mm - 1;
                const float* z = g_Z + (size_t)(b0 + w * 32 + bit) * DDIM;
                a0 += z[tid];
                a1 += z[tid + 256];
                a2 += z[tid + 512];
                a3 += z[tid + 768];
            }
        }
        __syncthreads();
    }
    g_dwT[(size_t)k * DDIM + tid]       = a0;
    g_dwT[(size_t)k * DDIM + tid + 256] = a1;
    g_dwT[(size_t)k * DDIM + tid + 512] = a2;
    g_dwT[(size_t)k * DDIM + tid + 768] = a3;
}

// new_embeddings[d,k] = (0.99*ema_dw[d,k] + 0.01*dwT[k,d]) / cs_stable[k]  (tiled transpose)
__global__ void emb_out_kernel(const float* __restrict__ ema_dw, float* __restrict__ out) {
    __shared__ float t[32][33];
    int k0 = blockIdx.x * 32, d0 = blockIdx.y * 32;
    int tx = threadIdx.x, ty = threadIdx.y;   // block (32,8)
#pragma unroll
    for (int i = 0; i < 4; i++)
        t[ty + i * 8][tx] = g_dwT[(size_t)(k0 + ty + i * 8) * DDIM + d0 + tx];
    __syncthreads();
#pragma unroll
    for (int i = 0; i < 4; i++) {
        int d = d0 + ty + i * 8;
        int k = k0 + tx;
        float v = 0.99f * ema_dw[(size_t)d * KCB + k] + 0.01f * t[tx][ty + i * 8];
        out[OUT_EMB + (size_t)d * KCB + k] = v / g_cs[k];
    }
}

// ---------------- launcher ----------------
extern "C" void kernel_launch(void* const* d_in, const int* in_sizes, int n_in,
                              void* d_out, int out_size) {
    const float* obs    = (const float*)d_in[0];
    const float* action = (const float*)d_in[1];
    const float* nobs   = (const float*)d_in[2];
    const float* rew    = (const float*)d_in[3];
    const float* term   = (const float*)d_in[4];
    const float* w0 = (const float*)d_in[5];
    const float* b0 = (const float*)d_in[6];
    const float* w1 = (const float*)d_in[7];
    const float* b1 = (const float*)d_in[8];
    const float* w2 = (const float*)d_in[9];
    const float* b2 = (const float*)d_in[10];
    const float* w3 = (const float*)d_in[11];
    const float* b3 = (const float*)d_in[12];
    const float* wl = (const float*)d_in[13];
    const float* bl = (const float*)d_in[14];
    const float* emb    = (const float*)d_in[15];
    const float* ema_cs = (const float*)d_in[16];
    const float* ema_dw = (const float*)d_in[17];
    float* out = (float*)d_out;

    float *pX0, *pW0p, *pA1, *pA2, *pZ, *pS;
    cudaGetSymbolAddress((void**)&pX0,  g_X0);
    cudaGetSymbolAddress((void**)&pW0p, g_W0p);
    cudaGetSymbolAddress((void**)&pA1,  g_A1);
    cudaGetSymbolAddress((void**)&pA2,  g_A2);
    cudaGetSymbolAddress((void**)&pZ,   g_Z);
    cudaGetSymbolAddress((void**)&pS,   g_S);

    zero_counts_kernel<<<2, 256>>>();
    pack_x0_kernel<<<dim3(9, BATCH), 128>>>(obs, action, nobs, rew, term);
    pack_w0_kernel<<<dim3(32, DINP), 128>>>(w0);
    prep_et_kernel<<<dim3(KCB / 32, DDIM / 32), dim3(32, 8)>>>(emb);
    prep_e2_kernel<<<2, 256>>>(emb);

    // MLP encoder
    sgemm_kernel<true ><<<dim3(HDIM / 128, BATCH / 128), 256>>>(pX0, pW0p, b0, pA1, HDIM, DINP);
    sgemm_kernel<true ><<<dim3(HDIM / 128, BATCH / 128), 256>>>(pA1, w1,   b1, pA2, HDIM, HDIM);
    sgemm_kernel<true ><<<dim3(HDIM / 128, BATCH / 128), 256>>>(pA2, w2,   b2, pA1, HDIM, HDIM);
    sgemm_kernel<true ><<<dim3(HDIM / 128, BATCH / 128), 256>>>(pA1, w3,   b3, pA2, HDIM, HDIM);
    sgemm_kernel<false><<<dim3(DDIM / 128, BATCH / 128), 256>>>(pA2, wl,   bl, pZ,  DDIM, HDIM);

    // S = z @ embeddings  ([D,K] row-major == GEMM B operand directly)
    sgemm_kernel<false><<<dim3(KCB / 128, BATCH / 128), 256>>>(pZ, emb, nullptr, pS, KCB, DDIM);

    // VQ tail
    vq_row_kernel<<<BATCH, 128>>>(out);
    vq_stats_kernel<<<1, 512>>>(ema_cs, out);
    vq_dw_kernel<<<KCB, 256>>>();
    emb_out_kernel<<<dim3(KCB / 32, DDIM / 32), dim3(32, 8)>>>(ema_dw, out);
}

// round 2
// speedup vs baseline: 1.0080x; 1.0080x over previous
#include <cuda_runtime.h>
#include <math.h>
#include <stdint.h>

// ---------------- problem constants ----------------
#define BATCH 16384
#define HDIM  4096
#define DDIM  1024
#define KCB   512
#define DIN   1090
#define DINP  1152   // padded input dim (multiple of 128)

// output layout (tuple flattened): q_st, loss, perplexity, new_embeddings, cs_stable
#define OUT_Q    0
#define OUT_LOSS 16777216
#define OUT_PERP 16777217
#define OUT_EMB  16777218
#define OUT_CS   17301506

// ---------------- scratch (device globals; no allocation) ----------------
__device__ float g_X0 [BATCH * DINP];
__device__ float g_W0p[DINP * HDIM];
__device__ float g_A1 [BATCH * HDIM];
__device__ float g_A2 [BATCH * HDIM];
__device__ float g_Z  [BATCH * DDIM];
__device__ float g_S  [BATCH * KCB];
__device__ float g_ET [KCB * DDIM];
__device__ float g_e2 [KCB];
__device__ int   g_idx[BATCH];
__device__ float g_counts[KCB];
__device__ float g_cs [KCB];
__device__ float g_rowloss[BATCH];
__device__ float g_dwT[KCB * DDIM];

// ---------------- small prep kernels ----------------
__global__ void zero_counts_kernel() {
    g_counts[blockIdx.x * 256 + threadIdx.x] = 0.0f;
}

// build padded hstack [B, 1152]
__global__ void pack_x0_kernel(const float* __restrict__ obs,
                               const float* __restrict__ act,
                               const float* __restrict__ nobs,
                               const float* __restrict__ rew,
                               const float* __restrict__ term) {
    int c = blockIdx.x * 128 + threadIdx.x;   // 0..1151 (grid.x = 9)
    int r = blockIdx.y;                        // 0..16383
    float v;
    if (c < 512)        v = obs [r * 512 + c];
    else if (c < 576)   v = act [r * 64  + (c - 512)];
    else if (c < 1088)  v = nobs[r * 512 + (c - 576)];
    else if (c == 1088) v = rew [r];
    else if (c == 1089) v = term[r];
    else                v = 0.0f;
    g_X0[(size_t)r * DINP + c] = v;
}

// pad w0 [1090,4096] -> [1152,4096]
__global__ void pack_w0_kernel(const float* __restrict__ w0) {
    int c = blockIdx.x * 128 + threadIdx.x;   // grid.x = 32
    int r = blockIdx.y;                        // 0..1151
    g_W0p[(size_t)r * HDIM + c] = (r < DIN) ? w0[(size_t)r * HDIM + c] : 0.0f;
}

// ET[k][d] = E[d][k]  (tiled transpose)
__global__ void prep_et_kernel(const float* __restrict__ E) {
    __shared__ float t[32][33];
    int k0 = blockIdx.x * 32, d0 = blockIdx.y * 32;
    int tx = threadIdx.x, ty = threadIdx.y;   // block (32,8)
#pragma unroll
    for (int i = 0; i < 4; i++)
        t[ty + i * 8][tx] = E[(size_t)(d0 + ty + i * 8) * KCB + k0 + tx];
    __syncthreads();
#pragma unroll
    for (int i = 0; i < 4; i++)
        g_ET[(size_t)(k0 + ty + i * 8) * DDIM + d0 + tx] = t[tx][ty + i * 8];
}

// e2[k] = sum_d E[d][k]^2
__global__ void prep_e2_kernel(const float* __restrict__ E) {
    int k = blockIdx.x * 256 + threadIdx.x;   // grid.x = 2
    float s = 0.0f;
    for (int d = 0; d < DDIM; d++) {
        float v = E[(size_t)d * KCB + k];
        s = fmaf(v, v, s);
    }
    g_e2[k] = s;
}

// ---------------- SGEMM: C[M,N] = A[M,K] @ B[K,N] (+bias)(+relu) ----------------
// 128x128 CTA tile, BK=8, 256 threads, 8x8 per thread.
template<bool RELU>
__global__ __launch_bounds__(256, 2)
void sgemm_kernel(const float* __restrict__ A, const float* __restrict__ B,
                  const float* __restrict__ bias, float* __restrict__ C,
                  int N, int K) {
    __shared__ float As[8][128];
    __shared__ float Bs[8][128];
    const int tid = threadIdx.x;
    const int bx = blockIdx.x, by = blockIdx.y;
    const float* Ab = A + (size_t)by * 128 * K;
    const float* Bb = B + (size_t)bx * 128;
    const int aRow = tid >> 1, aCol = (tid & 1) * 4;
    const int bRow = tid >> 5, bCol = (tid & 31) * 4;
    const int tx = (tid & 15) * 8, ty = (tid >> 4) * 8;
    float acc[8][8] = {};

    for (int kt = 0; kt < K; kt += 8) {
        float4 av = *reinterpret_cast<const float4*>(Ab + (size_t)aRow * K + kt + aCol);
        float4 bv = *reinterpret_cast<const float4*>(Bb + (size_t)(kt + bRow) * N + bCol);
        As[aCol + 0][aRow] = av.x;
        As[aCol + 1][aRow] = av.y;
        As[aCol + 2][aRow] = av.z;
        As[aCol + 3][aRow] = av.w;
        *reinterpret_cast<float4*>(&Bs[bRow][bCol]) = bv;
        __syncthreads();
#pragma unroll
        for (int kk = 0; kk < 8; kk++) {
            float a[8], b[8];
            *reinterpret_cast<float4*>(&a[0]) = *reinterpret_cast<const float4*>(&As[kk][ty]);
            *reinterpret_cast<float4*>(&a[4]) = *reinterpret_cast<const float4*>(&As[kk][ty + 4]);
            *reinterpret_cast<float4*>(&b[0]) = *reinterpret_cast<const float4*>(&Bs[kk][tx]);
            *reinterpret_cast<float4*>(&b[4]) = *reinterpret_cast<const float4*>(&Bs[kk][tx + 4]);
#pragma unroll
            for (int i = 0; i < 8; i++)
#pragma unroll
                for (int j = 0; j < 8; j++)
                    acc[i][j] = fmaf(a[i], b[j], acc[i][j]);
        }
        __syncthreads();
    }

    float bb[8];
#pragma unroll
    for (int j = 0; j < 8; j++) bb[j] = bias ? bias[bx * 128 + tx + j] : 0.0f;
#pragma unroll
    for (int i = 0; i < 8; i++) {
        float o[8];
#pragma unroll
        for (int j = 0; j < 8; j++) {
            float v = acc[i][j] + bb[j];
            if (RELU) v = fmaxf(v, 0.0f);
            o[j] = v;
        }
        float* Cp = C + (size_t)(by * 128 + ty + i) * N + bx * 128 + tx;
        *reinterpret_cast<float4*>(Cp)     = *reinterpret_cast<float4*>(&o[0]);
        *reinterpret_cast<float4*>(Cp + 4) = *reinterpret_cast<float4*>(&o[4]);
    }
}

// ---------------- VQ: per-row argmin + gather + loss partial + histogram ----------------
__global__ void vq_row_kernel(float* __restrict__ qout) {
    const int row = blockIdx.x;
    const int tid = threadIdx.x;              // 128 threads
    const float* Sr = g_S + (size_t)row * KCB;

    float best = 3.4e38f;
    int   bi   = 0;
    for (int k = tid; k < KCB; k += 128) {
        float dv = fmaf(-2.0f, Sr[k], g_e2[k]);   // ||z||^2 term is row-constant
        if (dv < best) { best = dv; bi = k; }
    }
    __shared__ float sv[128];
    __shared__ int   si[128];
    sv[tid] = best; si[tid] = bi;
    __syncthreads();
    for (int s = 64; s > 0; s >>= 1) {
        if (tid < s) {
            float ov = sv[tid + s]; int oi = si[tid + s];
            if (ov < sv[tid] || (ov == sv[tid] && oi < si[tid])) { sv[tid] = ov; si[tid] = oi; }
        }
        __syncthreads();
    }
    const int idx = si[0];
    if (tid == 0) {
        g_idx[row] = idx;
        atomicAdd(&g_counts[idx], 1.0f);   // integer counts: exact regardless of order
    }

    const float* e = g_ET + (size_t)idx * DDIM;
    const float* z = g_Z  + (size_t)row * DDIM;
    float ls = 0.0f;
    for (int d = tid; d < DDIM; d += 128) {
        float q = e[d], zz = z[d];
        qout[(size_t)row * DDIM + d] = q;
        float t = q - zz;
        ls = fmaf(t, t, ls);
    }
    __syncthreads();
    sv[tid] = ls;
    __syncthreads();
    for (int s = 64; s > 0; s >>= 1) {
        if (tid < s) sv[tid] += sv[tid + s];
        __syncthreads();
    }
    if (tid == 0) g_rowloss[row] = sv[0];
}

// ---------------- stats: n, perplexity, loss, cs_stable ----------------
__global__ void vq_stats_kernel(const float* __restrict__ ema_cs, float* __restrict__ out) {
    const int k = threadIdx.x;                // 512 threads, 1 block
    __shared__ float red[512];
    __shared__ float shn, shent;

    float cnt = g_counts[k];
    float cs  = 0.99f * ema_cs[k] + 0.01f * cnt;

    red[k] = cs; __syncthreads();
    for (int s = 256; s > 0; s >>= 1) { if (k < s) red[k] += red[k + s]; __syncthreads(); }
    if (k == 0) shn = red[0];
    __syncthreads();

    float p = cnt * (1.0f / 16384.0f);
    red[k] = p * logf(p + 1e-10f);
    __syncthreads();
    for (int s = 256; s > 0; s >>= 1) { if (k < s) red[k] += red[k + s]; __syncthreads(); }
    if (k == 0) shent = red[0];
    __syncthreads();

    float ls = 0.0f;
    for (int r = k; r < BATCH; r += 512) ls += g_rowloss[r];
    red[k] = ls; __syncthreads();
    for (int s = 256; s > 0; s >>= 1) { if (k < s) red[k] += red[k + s]; __syncthreads(); }

    float n   = shn;
    float csn = (cs + 1e-5f) / (n + 512.0f * 1e-5f) * n;
    g_cs[k] = csn;
    out[OUT_CS + k] = csn;
    if (k == 0) {
        out[OUT_LOSS] = 0.25f * red[0] / 16777216.0f;   // / (B*D)
        out[OUT_PERP] = expf(-shent);
    }
}

// ---------------- dw = z.T @ enc, deterministic ballot scan ----------------
// one block per codebook entry k; rows processed in ascending order -> fixed fp32 sum order
__global__ void vq_dw_kernel() {
    const int k = blockIdx.x;
    const int tid = threadIdx.x;              // 256 threads
    float a0 = 0.f, a1 = 0.f, a2 = 0.f, a3 = 0.f;
    __shared__ unsigned smask[8];

    for (int b0 = 0; b0 < BATCH; b0 += 256) {
        int mi = g_idx[b0 + tid];
        unsigned m = __ballot_sync(0xffffffffu, mi == k);
        if ((tid & 31) == 0) smask[tid >> 5] = m;
        __syncthreads();
#pragma unroll
        for (int w = 0; w < 8; w++) {
            unsigned mm = smask[w];
            while (mm) {
                int bit = __ffs(mm) - 1;
                mm &= mm - 1;
                const float* z = g_Z + (size_t)(b0 + w * 32 + bit) * DDIM;
                a0 += z[tid];
                a1 += z[tid + 256];
                a2 += z[tid + 512];
                a3 += z[tid + 768];
            }
        }
        __syncthreads();
    }
    g_dwT[(size_t)k * DDIM + tid]       = a0;
    g_dwT[(size_t)k * DDIM + tid + 256] = a1;
    g_dwT[(size_t)k * DDIM + tid + 512] = a2;
    g_dwT[(size_t)k * DDIM + tid + 768] = a3;
}

// new_embeddings[d,k] = (0.99*ema_dw[d,k] + 0.01*dwT[k,d]) / cs_stable[k]  (tiled transpose)
__global__ void emb_out_kernel(const float* __restrict__ ema_dw, float* __restrict__ out) {
    __shared__ float t[32][33];
    int k0 = blockIdx.x * 32, d0 = blockIdx.y * 32;
    int tx = threadIdx.x, ty = threadIdx.y;   // block (32,8)
#pragma unroll
    for (int i = 0; i < 4; i++)
        t[ty + i * 8][tx] = g_dwT[(size_t)(k0 + ty + i * 8) * DDIM + d0 + tx];
    __syncthreads();
#pragma unroll
    for (int i = 0; i < 4; i++) {
        int d = d0 + ty + i * 8;
        int k = k0 + tx;
        float v = 0.99f * ema_dw[(size_t)d * KCB + k] + 0.01f * t[tx][ty + i * 8];
        out[OUT_EMB + (size_t)d * KCB + k] = v / g_cs[k];
    }
}

// ---------------- launcher ----------------
extern "C" void kernel_launch(void* const* d_in, const int* in_sizes, int n_in,
                              void* d_out, int out_size) {
    const float* obs    = (const float*)d_in[0];
    const float* action = (const float*)d_in[1];
    const float* nobs   = (const float*)d_in[2];
    const float* rew    = (const float*)d_in[3];
    const float* term   = (const float*)d_in[4];
    const float* w0 = (const float*)d_in[5];
    const float* b0 = (const float*)d_in[6];
    const float* w1 = (const float*)d_in[7];
    const float* b1 = (const float*)d_in[8];
    const float* w2 = (const float*)d_in[9];
    const float* b2 = (const float*)d_in[10];
    const float* w3 = (const float*)d_in[11];
    const float* b3 = (const float*)d_in[12];
    const float* wl = (const float*)d_in[13];
    const float* bl = (const float*)d_in[14];
    const float* emb    = (const float*)d_in[15];
    const float* ema_cs = (const float*)d_in[16];
    const float* ema_dw = (const float*)d_in[17];
    float* out = (float*)d_out;

    float *pX0, *pW0p, *pA1, *pA2, *pZ, *pS;
    cudaGetSymbolAddress((void**)&pX0,  g_X0);
    cudaGetSymbolAddress((void**)&pW0p, g_W0p);
    cudaGetSymbolAddress((void**)&pA1,  g_A1);
    cudaGetSymbolAddress((void**)&pA2,  g_A2);
    cudaGetSymbolAddress((void**)&pZ,   g_Z);
    cudaGetSymbolAddress((void**)&pS,   g_S);

    zero_counts_kernel<<<2, 256>>>();
    pack_x0_kernel<<<dim3(9, BATCH), 128>>>(obs, action, nobs, rew, term);
    pack_w0_kernel<<<dim3(32, DINP), 128>>>(w0);
    prep_et_kernel<<<dim3(KCB / 32, DDIM / 32), dim3(32, 8)>>>(emb);
    prep_e2_kernel<<<2, 256>>>(emb);

    // MLP encoder
    sgemm_kernel<true ><<<dim3(HDIM / 128, BATCH / 128), 256>>>(pX0, pW0p, b0, pA1, HDIM, DINP);
    sgemm_kernel<true ><<<dim3(HDIM / 128, BATCH / 128), 256>>>(pA1, w1,   b1, pA2, HDIM, HDIM);
    sgemm_kernel<true ><<<dim3(HDIM / 128, BATCH / 128), 256>>>(pA2, w2,   b2, pA1, HDIM, HDIM);
    sgemm_kernel<true ><<<dim3(HDIM / 128, BATCH / 128), 256>>>(pA1, w3,   b3, pA2, HDIM, HDIM);
    sgemm_kernel<false><<<dim3(DDIM / 128, BATCH / 128), 256>>>(pA2, wl,   bl, pZ,  DDIM, HDIM);

    // S = z @ embeddings  ([D,K] row-major == GEMM B operand directly)
    sgemm_kernel<false><<<dim3(KCB / 128, BATCH / 128), 256>>>(pZ, emb, nullptr, pS, KCB, DDIM);

    // VQ tail
    vq_row_kernel<<<BATCH, 128>>>(out);
    vq_stats_kernel<<<1, 512>>>(ema_cs, out);
    vq_dw_kernel<<<KCB, 256>>>();
    emb_out_kernel<<<dim3(KCB / 32, DDIM / 32), dim3(32, 8)>>>(ema_dw, out);
}

// round 3
// speedup vs baseline: 1.0084x; 1.0003x over previous
#include <cuda_runtime.h>
#include <math.h>
#include <stdint.h>

// ---------------- problem constants ----------------
#define BATCH 16384
#define HDIM  4096
#define DDIM  1024
#define KCB   512
#define DIN   1090
#define DINP  1152   // padded input dim (multiple of 128)

// output layout (tuple flattened): q_st, loss, perplexity, new_embeddings, cs_stable
#define OUT_Q    0
#define OUT_LOSS 16777216
#define OUT_PERP 16777217
#define OUT_EMB  16777218
#define OUT_CS   17301506

// ---------------- scratch (device globals; no allocation) ----------------
__device__ float g_X0 [BATCH * DINP];
__device__ float g_W0p[DINP * HDIM];
__device__ float g_A1 [BATCH * HDIM];
__device__ float g_A2 [BATCH * HDIM];
__device__ float g_Z  [BATCH * DDIM];
__device__ float g_S  [BATCH * KCB];
__device__ float g_ET [KCB * DDIM];
__device__ float g_e2 [KCB];
__device__ int   g_idx[BATCH];
__device__ float g_counts[KCB];
__device__ float g_cs [KCB];
__device__ float g_rowloss[BATCH];
__device__ float g_dwT[KCB * DDIM];

// ---------------- small prep kernels ----------------
__global__ void zero_counts_kernel() {
    g_counts[blockIdx.x * 256 + threadIdx.x] = 0.0f;
}

// build padded hstack [B, 1152]
__global__ void pack_x0_kernel(const float* __restrict__ obs,
                               const float* __restrict__ act,
                               const float* __restrict__ nobs,
                               const float* __restrict__ rew,
                               const float* __restrict__ term) {
    int c = blockIdx.x * 128 + threadIdx.x;   // 0..1151 (grid.x = 9)
    int r = blockIdx.y;                        // 0..16383
    float v;
    if (c < 512)        v = obs [r * 512 + c];
    else if (c < 576)   v = act [r * 64  + (c - 512)];
    else if (c < 1088)  v = nobs[r * 512 + (c - 576)];
    else if (c == 1088) v = rew [r];
    else if (c == 1089) v = term[r];
    else                v = 0.0f;
    g_X0[(size_t)r * DINP + c] = v;
}

// pad w0 [1090,4096] -> [1152,4096]
__global__ void pack_w0_kernel(const float* __restrict__ w0) {
    int c = blockIdx.x * 128 + threadIdx.x;   // grid.x = 32
    int r = blockIdx.y;                        // 0..1151
    g_W0p[(size_t)r * HDIM + c] = (r < DIN) ? w0[(size_t)r * HDIM + c] : 0.0f;
}

// ET[k][d] = E[d][k]  (tiled transpose)
__global__ void prep_et_kernel(const float* __restrict__ E) {
    __shared__ float t[32][33];
    int k0 = blockIdx.x * 32, d0 = blockIdx.y * 32;
    int tx = threadIdx.x, ty = threadIdx.y;   // block (32,8)
#pragma unroll
    for (int i = 0; i < 4; i++)
        t[ty + i * 8][tx] = E[(size_t)(d0 + ty + i * 8) * KCB + k0 + tx];
    __syncthreads();
#pragma unroll
    for (int i = 0; i < 4; i++)
        g_ET[(size_t)(k0 + ty + i * 8) * DDIM + d0 + tx] = t[tx][ty + i * 8];
}

// e2[k] = sum_d E[d][k]^2
__global__ void prep_e2_kernel(const float* __restrict__ E) {
    int k = blockIdx.x * 256 + threadIdx.x;   // grid.x = 2
    float s = 0.0f;
    for (int d = 0; d < DDIM; d++) {
        float v = E[(size_t)d * KCB + k];
        s = fmaf(v, v, s);
    }
    g_e2[k] = s;
}

// ---------------- SGEMM: C[M,N] = A[M,K] @ B[K,N] (+bias)(+relu) ----------------
// 128x128 CTA tile, BK=8, 256 threads, 8x8 per thread.
template<bool RELU>
__global__ __launch_bounds__(256, 2)
void sgemm_kernel(const float* __restrict__ A, const float* __restrict__ B,
                  const float* __restrict__ bias, float* __restrict__ C,
                  int N, int K) {
    __shared__ float As[8][128];
    __shared__ float Bs[8][128];
    const int tid = threadIdx.x;
    const int bx = blockIdx.x, by = blockIdx.y;
    const float* Ab = A + (size_t)by * 128 * K;
    const float* Bb = B + (size_t)bx * 128;
    const int aRow = tid >> 1, aCol = (tid & 1) * 4;
    const int bRow = tid >> 5, bCol = (tid & 31) * 4;
    const int tx = (tid & 15) * 8, ty = (tid >> 4) * 8;
    float acc[8][8] = {};

    for (int kt = 0; kt < K; kt += 8) {
        float4 av = *reinterpret_cast<const float4*>(Ab + (size_t)aRow * K + kt + aCol);
        float4 bv = *reinterpret_cast<const float4*>(Bb + (size_t)(kt + bRow) * N + bCol);
        As[aCol + 0][aRow] = av.x;
        As[aCol + 1][aRow] = av.y;
        As[aCol + 2][aRow] = av.z;
        As[aCol + 3][aRow] = av.w;
        *reinterpret_cast<float4*>(&Bs[bRow][bCol]) = bv;
        __syncthreads();
#pragma unroll
        for (int kk = 0; kk < 8; kk++) {
            float a[8], b[8];
            *reinterpret_cast<float4*>(&a[0]) = *reinterpret_cast<const float4*>(&As[kk][ty]);
            *reinterpret_cast<float4*>(&a[4]) = *reinterpret_cast<const float4*>(&As[kk][ty + 4]);
            *reinterpret_cast<float4*>(&b[0]) = *reinterpret_cast<const float4*>(&Bs[kk][tx]);
            *reinterpret_cast<float4*>(&b[4]) = *reinterpret_cast<const float4*>(&Bs[kk][tx + 4]);
#pragma unroll
            for (int i = 0; i < 8; i++)
#pragma unroll
                for (int j = 0; j < 8; j++)
                    acc[i][j] = fmaf(a[i], b[j], acc[i][j]);
        }
        __syncthreads();
    }

    float bb[8];
#pragma unroll
    for (int j = 0; j < 8; j++) bb[j] = bias ? bias[bx * 128 + tx + j] : 0.0f;
#pragma unroll
    for (int i = 0; i < 8; i++) {
        float o[8];
#pragma unroll
        for (int j = 0; j < 8; j++) {
            float v = acc[i][j] + bb[j];
            if (RELU) v = fmaxf(v, 0.0f);
            o[j] = v;
        }
        float* Cp = C + (size_t)(by * 128 + ty + i) * N + bx * 128 + tx;
        *reinterpret_cast<float4*>(Cp)     = *reinterpret_cast<float4*>(&o[0]);
        *reinterpret_cast<float4*>(Cp + 4) = *reinterpret_cast<float4*>(&o[4]);
    }
}

// ---------------- VQ: per-row argmin + gather + loss partial + histogram ----------------
__global__ void vq_row_kernel(float* __restrict__ qout) {
    const int row = blockIdx.x;
    const int tid = threadIdx.x;              // 128 threads
    const float* Sr = g_S + (size_t)row * KCB;

    float best = 3.4e38f;
    int   bi   = 0;
    for (int k = tid; k < KCB; k += 128) {
        float dv = fmaf(-2.0f, Sr[k], g_e2[k]);   // ||z||^2 term is row-constant
        if (dv < best) { best = dv; bi = k; }
    }
    __shared__ float sv[128];
    __shared__ int   si[128];
    sv[tid] = best; si[tid] = bi;
    __syncthreads();
    for (int s = 64; s > 0; s >>= 1) {
        if (tid < s) {
            float ov = sv[tid + s]; int oi = si[tid + s];
            if (ov < sv[tid] || (ov == sv[tid] && oi < si[tid])) { sv[tid] = ov; si[tid] = oi; }
        }
        __syncthreads();
    }
    const int idx = si[0];
    if (tid == 0) {
        g_idx[row] = idx;
        atomicAdd(&g_counts[idx], 1.0f);   // integer counts: exact regardless of order
    }

    const float* e = g_ET + (size_t)idx * DDIM;
    const float* z = g_Z  + (size_t)row * DDIM;
    float ls = 0.0f;
    for (int d = tid; d < DDIM; d += 128) {
        float q = e[d], zz = z[d];
        qout[(size_t)row * DDIM + d] = q;
        float t = q - zz;
        ls = fmaf(t, t, ls);
    }
    __syncthreads();
    sv[tid] = ls;
    __syncthreads();
    for (int s = 64; s > 0; s >>= 1) {
        if (tid < s) sv[tid] += sv[tid + s];
        __syncthreads();
    }
    if (tid == 0) g_rowloss[row] = sv[0];
}

// ---------------- stats: n, perplexity, loss, cs_stable ----------------
__global__ void vq_stats_kernel(const float* __restrict__ ema_cs, float* __restrict__ out) {
    const int k = threadIdx.x;                // 512 threads, 1 block
    __shared__ float red[512];
    __shared__ float shn, shent;

    float cnt = g_counts[k];
    float cs  = 0.99f * ema_cs[k] + 0.01f * cnt;

    red[k] = cs; __syncthreads();
    for (int s = 256; s > 0; s >>= 1) { if (k < s) red[k] += red[k + s]; __syncthreads(); }
    if (k == 0) shn = red[0];
    __syncthreads();

    float p = cnt * (1.0f / 16384.0f);
    red[k] = p * logf(p + 1e-10f);
    __syncthreads();
    for (int s = 256; s > 0; s >>= 1) { if (k < s) red[k] += red[k + s]; __syncthreads(); }
    if (k == 0) shent = red[0];
    __syncthreads();

    float ls = 0.0f;
    for (int r = k; r < BATCH; r += 512) ls += g_rowloss[r];
    red[k] = ls; __syncthreads();
    for (int s = 256; s > 0; s >>= 1) { if (k < s) red[k] += red[k + s]; __syncthreads(); }

    float n   = shn;
    float csn = (cs + 1e-5f) / (n + 512.0f * 1e-5f) * n;
    g_cs[k] = csn;
    out[OUT_CS + k] = csn;
    if (k == 0) {
        out[OUT_LOSS] = 0.25f * red[0] / 16777216.0f;   // / (B*D)
        out[OUT_PERP] = expf(-shent);
    }
}

// ---------------- dw = z.T @ enc, deterministic ballot scan ----------------
// one block per codebook entry k; rows processed in ascending order -> fixed fp32 sum order
__global__ void vq_dw_kernel() {
    const int k = blockIdx.x;
    const int tid = threadIdx.x;              // 256 threads
    float a0 = 0.f, a1 = 0.f, a2 = 0.f, a3 = 0.f;
    __shared__ unsigned smask[8];

    for (int b0 = 0; b0 < BATCH; b0 += 256) {
        int mi = g_idx[b0 + tid];
        unsigned m = __ballot_sync(0xffffffffu, mi == k);
        if ((tid & 31) == 0) smask[tid >> 5] = m;
        __syncthreads();
#pragma unroll
        for (int w = 0; w < 8; w++) {
            unsigned mm = smask[w];
            while (mm) {
                int bit = __ffs(mm) - 1;
                mm &= mm - 1;
                const float* z = g_Z + (size_t)(b0 + w * 32 + bit) * DDIM;
                a0 += z[tid];
                a1 += z[tid + 256];
                a2 += z[tid + 512];
                a3 += z[tid + 768];
            }
        }
        __syncthreads();
    }
    g_dwT[(size_t)k * DDIM + tid]       = a0;
    g_dwT[(size_t)k * DDIM + tid + 256] = a1;
    g_dwT[(size_t)k * DDIM + tid + 512] = a2;
    g_dwT[(size_t)k * DDIM + tid + 768] = a3;
}

// new_embeddings[d,k] = (0.99*ema_dw[d,k] + 0.01*dwT[k,d]) / cs_stable[k]  (tiled transpose)
__global__ void emb_out_kernel(const float* __restrict__ ema_dw, float* __restrict__ out) {
    __shared__ float t[32][33];
    int k0 = blockIdx.x * 32, d0 = blockIdx.y * 32;
    int tx = threadIdx.x, ty = threadIdx.y;   // block (32,8)
#pragma unroll
    for (int i = 0; i < 4; i++)
        t[ty + i * 8][tx] = g_dwT[(size_t)(k0 + ty + i * 8) * DDIM + d0 + tx];
    __syncthreads();
#pragma unroll
    for (int i = 0; i < 4; i++) {
        int d = d0 + ty + i * 8;
        int k = k0 + tx;
        float v = 0.99f * ema_dw[(size_t)d * KCB + k] + 0.01f * t[tx][ty + i * 8];
        out[OUT_EMB + (size_t)d * KCB + k] = v / g_cs[k];
    }
}

// ---------------- launcher ----------------
extern "C" void kernel_launch(void* const* d_in, const int* in_sizes, int n_in,
                              void* d_out, int out_size) {
    const float* obs    = (const float*)d_in[0];
    const float* action = (const float*)d_in[1];
    const float* nobs   = (const float*)d_in[2];
    const float* rew    = (const float*)d_in[3];
    const float* term   = (const float*)d_in[4];
    const float* w0 = (const float*)d_in[5];
    const float* b0 = (const float*)d_in[6];
    const float* w1 = (const float*)d_in[7];
    const float* b1 = (const float*)d_in[8];
    const float* w2 = (const float*)d_in[9];
    const float* b2 = (const float*)d_in[10];
    const float* w3 = (const float*)d_in[11];
    const float* b3 = (const float*)d_in[12];
    const float* wl = (const float*)d_in[13];
    const float* bl = (const float*)d_in[14];
    const float* emb    = (const float*)d_in[15];
    const float* ema_cs = (const float*)d_in[16];
    const float* ema_dw = (const float*)d_in[17];
    float* out = (float*)d_out;

    float *pX0, *pW0p, *pA1, *pA2, *pZ, *pS;
    cudaGetSymbolAddress((void**)&pX0,  g_X0);
    cudaGetSymbolAddress((void**)&pW0p, g_W0p);
    cudaGetSymbolAddress((void**)&pA1,  g_A1);
    cudaGetSymbolAddress((void**)&pA2,  g_A2);
    cudaGetSymbolAddress((void**)&pZ,   g_Z);
    cudaGetSymbolAddress((void**)&pS,   g_S);

    zero_counts_kernel<<<2, 256>>>();
    pack_x0_kernel<<<dim3(9, BATCH), 128>>>(obs, action, nobs, rew, term);
    pack_w0_kernel<<<dim3(32, DINP), 128>>>(w0);
    prep_et_kernel<<<dim3(KCB / 32, DDIM / 32), dim3(32, 8)>>>(emb);
    prep_e2_kernel<<<2, 256>>>(emb);

    // MLP encoder
    sgemm_kernel<true ><<<dim3(HDIM / 128, BATCH / 128), 256>>>(pX0, pW0p, b0, pA1, HDIM, DINP);
    sgemm_kernel<true ><<<dim3(HDIM / 128, BATCH / 128), 256>>>(pA1, w1,   b1, pA2, HDIM, HDIM);
    sgemm_kernel<true ><<<dim3(HDIM / 128, BATCH / 128), 256>>>(pA2, w2,   b2, pA1, HDIM, HDIM);
    sgemm_kernel<true ><<<dim3(HDIM / 128, BATCH / 128), 256>>>(pA1, w3,   b3, pA2, HDIM, HDIM);
    sgemm_kernel<false><<<dim3(DDIM / 128, BATCH / 128), 256>>>(pA2, wl,   bl, pZ,  DDIM, HDIM);

    // S = z @ embeddings  ([D,K] row-major == GEMM B operand directly)
    sgemm_kernel<false><<<dim3(KCB / 128, BATCH / 128), 256>>>(pZ, emb, nullptr, pS, KCB, DDIM);

    // VQ tail
    vq_row_kernel<<<BATCH, 128>>>(out);
    vq_stats_kernel<<<1, 512>>>(ema_cs, out);
    vq_dw_kernel<<<KCB, 256>>>();
    emb_out_kernel<<<dim3(KCB / 32, DDIM / 32), dim3(32, 8)>>>(ema_dw, out);
}